// round 14
// baseline (speedup 1.0000x reference)
#include <cuda_runtime.h>
#include <cstdint>

#define NSESS    4096
#define NTRIALS  2048
#define NWORDS   (NTRIALS / 32)        // 64 packed words per session

// filter chunking
#define FCHUNK   64                    // output trials per warp (2 packed words)
#define FNCHUNK  (NTRIALS / FCHUNK)    // 32 chunks
#define FWARM    16                    // warmup trials (validated: rel_err ~6e-5)

// packed bits: bit i of packed[w*NSESS+s] = (chose_left==outcome) at trial w*32+i
__device__ uint32_t g_packed[NWORDS * NSESS];

__device__ __forceinline__ float frcp_fast(float x) {
    float y;
    asm("rcp.approx.f32 %0, %1;" : "=f"(y) : "f"(x));
    return y;
}

__device__ __forceinline__ void cp_async16(uint32_t dst, const void* src) {
    asm volatile("cp.async.cg.shared.global [%0], [%1], 16;\n" :: "r"(dst), "l"(src));
}
__device__ __forceinline__ void cp_commit() {
    asm volatile("cp.async.commit_group;\n" ::: "memory");
}
template <int N>
__device__ __forceinline__ void cp_wait() {
    asm volatile("cp.async.wait_group %0;\n" :: "n"(N) : "memory");
}

// ---------------------------------------------------------------------------
// Kernel 1: pack, 4-deep prefetch. One warp per QUARTER-session (4 tiles of
// 1536 B). All 4 tiles issued up front (6 KB in flight/warp), drained with
// progressively shallower wait_group. R5-proven nibble+shuffle assembly.
// ---------------------------------------------------------------------------
#define PTILE 1536

__global__ void __launch_bounds__(128)
pack_kernel(const float* __restrict__ in, uint32_t* __restrict__ packed) {
    __shared__ __align__(16) char buf[4][4][PTILE];   // 24576 B

    const int lane  = threadIdx.x & 31;
    const int wid   = threadIdx.x >> 5;
    const int gwarp = blockIdx.x * 4 + wid;
    const int s     = gwarp >> 2;
    const int quart = gwarp & 3;

    const char* src = (const char*)in + (long)s * (NTRIALS * 12) + quart * (512 * 12);
    const uint32_t sbase = (uint32_t)__cvta_generic_to_shared(&buf[wid][0][0]);

    // issue all 4 tiles up front, one commit group each
#pragma unroll
    for (int t = 0; t < 4; t++) {
#pragma unroll
        for (int r = 0; r < 3; r++)
            cp_async16(sbase + t * PTILE + r * 512 + lane * 16,
                       src + t * PTILE + r * 512 + lane * 16);
        cp_commit();
    }

#pragma unroll
    for (int t = 0; t < 4; t++) {
        switch (t) {
            case 0: cp_wait<3>(); break;
            case 1: cp_wait<2>(); break;
            case 2: cp_wait<1>(); break;
            default: cp_wait<0>(); break;
        }
        __syncwarp();

        const float4* rp = (const float4*)(&buf[wid][t][0] + 48 * lane);
        float4 x0 = rp[0];   // cl0 cr0 o0  cl1
        float4 x1 = rp[1];   // cr1 o1  cl2 cr2
        float4 x2 = rp[2];   // o2  cl3 cr3 o3

        int b0 = (x0.x == x0.z);
        int b1 = (x0.w == x1.y);
        int b2 = (x1.z == x2.x);
        int b3 = (x2.y == x2.w);
        uint32_t nib = (uint32_t)(b0 | (b1 << 1) | (b2 << 2) | (b3 << 3));
        uint32_t v = nib << ((lane & 7) * 4);
        v |= __shfl_xor_sync(0xFFFFFFFFu, v, 1);
        v |= __shfl_xor_sync(0xFFFFFFFFu, v, 2);
        v |= __shfl_xor_sync(0xFFFFFFFFu, v, 4);
        if ((lane & 7) == 0) {
            int w = quart * 16 + t * 4 + (lane >> 3);
            packed[w * NSESS + s] = v;
        }
    }
}

// ---------------------------------------------------------------------------
// Kernel 2: filter (R12 math, FCHUNK=64). One warp = 32 sessions x one
// 64-trial chunk (+16 warmup). 4096 warps; 80 steps/warp.
// ---------------------------------------------------------------------------
#define ROW_F4 9
#define WARP_F4 (32 * ROW_F4)

__global__ void __launch_bounds__(128, 10)
filter_kernel(const uint32_t* __restrict__ packed,
              const float* __restrict__ p_stay_raw,
              const float* __restrict__ c_raw,
              float* __restrict__ out) {
    __shared__ float4 stage4[4 * WARP_F4];   // 18432 B

    const int lane  = threadIdx.x & 31;
    const int wid   = threadIdx.x >> 5;
    const int gwarp = blockIdx.x * 4 + wid;
    const int chunk = gwarp & (FNCHUNK - 1);
    const int sess0 = (gwarp >> 5) * 32;     // FNCHUNK == 32

    // packed words: 2 output words + 1 warmup word (high half)
    const int w0 = chunk * 2;
    const uint32_t wc0 = packed[w0 * NSESS + sess0 + lane];
    const uint32_t wc1 = packed[(w0 + 1) * NSESS + sess0 + lane];
    const uint32_t wprev = (chunk > 0)
        ? packed[(w0 - 1) * NSESS + sess0 + lane] : 0u;

    const float pv = 1.0f / (1.0f + __expf(-p_stay_raw[0]));
    const float cv = 1.0f / (1.0f + __expf(-c_raw[0]));
    const float A  = 0.5f * (1.0f + cv);
    const float B  = 0.5f * (1.0f - cv);
    const float q  = 0.5f * (1.0f + pv);
    const float qm = 0.5f * (1.0f - pv);

    float4* ws4 = stage4 + wid * WARP_F4;
    float4* ob4 = ws4 + lane * ROW_F4;

    float v0 = 0.5f, v1 = 0.5f;

    // ---- warmup: high 16 bits of previous word, renorm once ----
    if (chunk > 0) {
#pragma unroll
        for (int i = 0; i < FWARM; i++) {
            float e0 = ((wprev >> (16 + i)) & 1u) ? A : B;
            float u0 = e0 * v0;
            float u1 = fmaf(-e0, v1, v1);
            float s  = u0 + u1;
            float a  = fmaf(q, u0, qm * u1);
            v0 = a;
            v1 = s - a;
        }
        float r = frcp_fast(v0 + v1);
        v0 *= r; v1 *= r;
    }

    // ---- output: 2 words x 2 halves of 16 trials ----
#pragma unroll
    for (int k = 0; k < 2; k++) {
        const uint32_t wcur = k ? wc1 : wc0;
#pragma unroll
        for (int h = 0; h < 2; h++) {
            float r_mid = 1.0f;
            float px = 0.0f;
#pragma unroll
            for (int i = 0; i < 16; i++) {
                float e0 = ((wcur >> (h * 16 + i)) & 1u) ? A : B;
                float u0 = e0 * v0;
                float u1 = fmaf(-e0, v1, v1);
                float s  = u0 + u1;
                float a  = fmaf(q, u0, qm * u1);
                float r  = frcp_fast(s);       // off-chain: outputs only
                float x  = a * r;
                if (i & 1) {
                    ob4[i >> 1] = make_float4(px, 1.0f - px, x, 1.0f - x);
                } else {
                    px = x;
                }
                if (i == 7) r_mid = r;
                v0 = a;
                v1 = s - a;
            }
            v0 *= r_mid; v1 *= r_mid;          // keep magnitudes in range

            __syncwarp();
            const int T = chunk * FCHUNK + k * 32 + h * 16;
            float4* og4 = (float4*)out + (long)sess0 * (NTRIALS / 2) + (T >> 1);
#pragma unroll
            for (int j = 0; j < 8; j++) {
                int idx = j * 32 + lane;
                int row = idx >> 3;
                int col = idx & 7;
                og4[(long)row * (NTRIALS / 2) + col] = ws4[row * ROW_F4 + col];
            }
            __syncwarp();
        }
    }
}

extern "C" void kernel_launch(void* const* d_in, const int* in_sizes, int n_in,
                              void* d_out, int out_size) {
    const float* in   = (const float*)d_in[0];
    const float* praw = (const float*)d_in[1];
    const float* craw = (const float*)d_in[2];
    float* out = (float*)d_out;

    uint32_t* packed = nullptr;
    cudaGetSymbolAddress((void**)&packed, g_packed);

    pack_kernel<<<NSESS, 128>>>(in, packed);                                     // 16384 warps
    filter_kernel<<<(NSESS / 32) * FNCHUNK / 4, 128>>>(packed, praw, craw, out); // 4096 warps
}